// round 2
// baseline (speedup 1.0000x reference)
#include <cuda_runtime.h>
#include <cuda_bf16.h>

// BSplineBasis, uniform knots. out[b,s] = P_{i(x)}(u(x)) with per-(spline,interval)
// cubic polynomial coefficients precomputed into smem as float4 (a,b,c,d).
// x: (4096,4096) f32, coefficients: (4096,8) f32, grid: (12,) f32 uniform.

#define S_TOTAL 4096
#define B_TOTAL 4096
#define THREADS 128
#define SPT     4                    // splines per thread (float4 I/O)
#define TILE_S  (THREADS * SPT)      // 512 splines per block
#define GRID_X  (S_TOTAL / TILE_S)   // 8
#define GRID_Y  128
#define ROWS    (B_TOTAL / GRID_Y)   // 32

__global__ __launch_bounds__(THREADS)
void bspline_kernel(const float* __restrict__ x,
                    const float* __restrict__ coeff,
                    const float* __restrict__ grid,
                    float* __restrict__ out)
{
    // Per-spline, per-interval cubic polynomial coeffs: sc4[s_local*5 + w]
    __shared__ float4 sc4[TILE_S * 5];   // 512*5*16B = 40 KB

    const int t  = threadIdx.x;
    const int s0 = blockIdx.x * TILE_S;

    // ---- Stage: build polynomial table (once per block) ----
    #pragma unroll
    for (int j = 0; j < SPT; j++) {
        const int sl = t * SPT + j;
        const float4* crow = reinterpret_cast<const float4*>(coeff + (size_t)(s0 + sl) * 8);
        float4 A = crow[0], B = crow[1];
        float c8[8] = {A.x, A.y, A.z, A.w, B.x, B.y, B.z, B.w};
        #pragma unroll
        for (int w = 0; w < 5; w++) {
            float w0 = c8[w], w1 = c8[w+1], w2 = c8[w+2], w3 = c8[w+3];
            // Expand sum_m B_m(u) * c[w+m] into a + b*u + c*u^2 + d*u^3
            float pa = (w0 + 4.0f * w1 + w2) * (1.0f / 6.0f);
            float pb = (w2 - w0) * 0.5f;
            float pc = (w0 - 2.0f * w1 + w2) * 0.5f;
            float pd = (w3 - w0 + 3.0f * (w1 - w2)) * (1.0f / 6.0f);
            sc4[sl * 5 + w] = make_float4(pa, pb, pc, pd);
        }
    }
    __syncthreads();

    // ---- Main streaming loop ----
    const float g0   = __ldg(&grid[0]);
    const float invh = 1.0f / (__ldg(&grid[1]) - g0);
    const float c0h  = -g0 * invh;                 // t = x*invh + c0h

    const int b0 = blockIdx.y * ROWS;
    const int scol = s0 + t * SPT;
    const float* xp = x   + (size_t)b0 * S_TOTAL + scol;
    float*       op = out + (size_t)b0 * S_TOTAL + scol;
    const int slbase = t * SPT * 5;

    #pragma unroll 1
    for (int r = 0; r < ROWS; r += 4) {
        float4 xv[4];
        #pragma unroll
        for (int k = 0; k < 4; k++)
            xv[k] = *reinterpret_cast<const float4*>(xp + (size_t)(r + k) * S_TOTAL);

        #pragma unroll
        for (int k = 0; k < 4; k++) {
            float xq[4] = {xv[k].x, xv[k].y, xv[k].z, xv[k].w};
            float vq[4];
            #pragma unroll
            for (int j = 0; j < 4; j++) {
                float tt = fmaf(xq[j], invh, c0h);
                float fi = floorf(tt);
                fi = fminf(fmaxf(fi, 3.0f), 7.0f);
                float u  = tt - fi;
                int   w  = (int)fi - 3;            // 0..4
                float4 p = sc4[slbase + j * 5 + w];
                vq[j] = fmaf(fmaf(fmaf(p.w, u, p.z), u, p.y), u, p.x);
            }
            *reinterpret_cast<float4*>(op + (size_t)(r + k) * S_TOTAL) =
                make_float4(vq[0], vq[1], vq[2], vq[3]);
        }
    }
}

extern "C" void kernel_launch(void* const* d_in, const int* in_sizes, int n_in,
                              void* d_out, int out_size)
{
    const float* x     = (const float*)d_in[0];
    const float* coeff = (const float*)d_in[1];
    const float* grid  = (const float*)d_in[2];
    float*       out   = (float*)d_out;

    dim3 g(GRID_X, GRID_Y);   // (8, 128) = 1024 blocks
    bspline_kernel<<<g, THREADS>>>(x, coeff, grid, out);
}

// round 3
// speedup vs baseline: 1.1798x; 1.1798x over previous
#include <cuda_runtime.h>
#include <cuda_bf16.h>

// BSplineBasis, uniform knots. Each thread owns one spline column; its 5
// per-interval cubic polynomials (a,b,c,d) live in REGISTERS (no smem, no LDS).
// Interval pick = 4 FSETP + FSEL chains. Global I/O is the only L1 traffic.
// x: (4096,4096) f32, coefficients: (4096,8) f32, grid: (12,) f32 uniform.

#define S_TOTAL 4096
#define B_TOTAL 4096
#define THREADS 256
#define GRID_X  (S_TOTAL / THREADS)   // 16
#define GRID_Y  64
#define ROWS    (B_TOTAL / GRID_Y)    // 64
#define UN      8                     // row unroll (MLP)

__global__ __launch_bounds__(THREADS)
void bspline_kernel(const float* __restrict__ x,
                    const float* __restrict__ coeff,
                    const float* __restrict__ grid,
                    float* __restrict__ out)
{
    const int t = threadIdx.x;
    const int s = blockIdx.x * THREADS + t;

    // ---- Build per-interval polynomial table in registers ----
    const float4* crow = reinterpret_cast<const float4*>(coeff + (size_t)s * 8);
    float4 A = crow[0], Bq = crow[1];
    float c8[8] = {A.x, A.y, A.z, A.w, Bq.x, Bq.y, Bq.z, Bq.w};

    float pa[5], pb[5], pc[5], pd[5];
    #pragma unroll
    for (int w = 0; w < 5; w++) {
        float w0 = c8[w], w1 = c8[w+1], w2 = c8[w+2], w3 = c8[w+3];
        pa[w] = (w0 + 4.0f * w1 + w2) * (1.0f / 6.0f);
        pb[w] = (w2 - w0) * 0.5f;
        pc[w] = (w0 - 2.0f * w1 + w2) * 0.5f;
        pd[w] = (w3 - w0 + 3.0f * (w1 - w2)) * (1.0f / 6.0f);
    }

    const float g0   = __ldg(&grid[0]);
    const float invh = 1.0f / (__ldg(&grid[1]) - g0);
    const float c0h  = -g0 * invh;                 // tt = x*invh + c0h, in [3,8)

    const int b0 = blockIdx.y * ROWS;
    const float* xp = x   + (size_t)b0 * S_TOTAL + s;
    float*       op = out + (size_t)b0 * S_TOTAL + s;

    #pragma unroll 1
    for (int r = 0; r < ROWS; r += UN) {
        float xv[UN];
        #pragma unroll
        for (int k = 0; k < UN; k++)
            xv[k] = xp[(size_t)k * S_TOTAL];       // MLP = UN outstanding loads

        #pragma unroll
        for (int k = 0; k < UN; k++) {
            float tt = fmaf(xv[k], invh, c0h);
            float fi = floorf(tt);
            fi = fminf(fmaxf(fi, 3.0f), 7.0f);
            float u  = tt - fi;

            // 5-way register select via FSEL chains (predicates shared)
            bool q0 = fi < 3.5f, q1 = fi < 4.5f, q2 = fi < 5.5f, q3 = fi < 6.5f;
            float qa = q0 ? pa[0] : q1 ? pa[1] : q2 ? pa[2] : q3 ? pa[3] : pa[4];
            float qb = q0 ? pb[0] : q1 ? pb[1] : q2 ? pb[2] : q3 ? pb[3] : pb[4];
            float qc = q0 ? pc[0] : q1 ? pc[1] : q2 ? pc[2] : q3 ? pc[3] : pc[4];
            float qd = q0 ? pd[0] : q1 ? pd[1] : q2 ? pd[2] : q3 ? pd[3] : pd[4];

            float v = fmaf(fmaf(fmaf(qd, u, qc), u, qb), u, qa);
            op[(size_t)k * S_TOTAL] = v;
        }
        xp += (size_t)UN * S_TOTAL;
        op += (size_t)UN * S_TOTAL;
    }
}

extern "C" void kernel_launch(void* const* d_in, const int* in_sizes, int n_in,
                              void* d_out, int out_size)
{
    const float* x     = (const float*)d_in[0];
    const float* coeff = (const float*)d_in[1];
    const float* grid  = (const float*)d_in[2];
    float*       out   = (float*)d_out;

    dim3 g(GRID_X, GRID_Y);   // (16, 64) = 1024 blocks
    bspline_kernel<<<g, THREADS>>>(x, coeff, grid, out);
}

// round 7
// speedup vs baseline: 1.6098x; 1.3645x over previous
#include <cuda_runtime.h>
#include <cuda_bf16.h>

// BSplineBasis, uniform knots, truncated-power form (C^2 exact):
//   y = (x - grid[3]) / h  in [0,5)
//   out = A + B y + C y^2 + D y^3 + sum_{j=1..4} E_j * max(0, y-j)^3
// Only 8 table registers/thread; no selects, no floor, no clamp.
// x: (4096,4096) f32, coefficients: (4096,8) f32, grid: (12,) f32 uniform.

#define S_TOTAL 4096
#define B_TOTAL 4096
#define THREADS 256
#define GRID_X  (S_TOTAL / THREADS)   // 16
#define GRID_Y  128
#define ROWS    (B_TOTAL / GRID_Y)    // 32
#define UN      8                     // row unroll (MLP)

__global__ __launch_bounds__(THREADS)
void bspline_kernel(const float* __restrict__ x,
                    const float* __restrict__ coeff,
                    const float* __restrict__ grid,
                    float* __restrict__ out)
{
    const int t = threadIdx.x;
    const int s = blockIdx.x * THREADS + t;

    // ---- Build truncated-power table in registers ----
    const float4* crow = reinterpret_cast<const float4*>(coeff + (size_t)s * 8);
    float4 Aq = crow[0], Bq = crow[1];
    float c8[8] = {Aq.x, Aq.y, Aq.z, Aq.w, Bq.x, Bq.y, Bq.z, Bq.w};

    // Cubic-in-u coefficients per interval w: pd[w] is the u^3 coefficient.
    float pd[5];
    #pragma unroll
    for (int w = 0; w < 5; w++)
        pd[w] = (c8[w+3] - c8[w] + 3.0f * (c8[w+1] - c8[w+2])) * (1.0f / 6.0f);

    // Base cubic = interval-0 polynomial (u == y there).
    const float A = (c8[0] + 4.0f * c8[1] + c8[2]) * (1.0f / 6.0f);
    const float B = (c8[2] - c8[0]) * 0.5f;
    const float C = (c8[0] - 2.0f * c8[1] + c8[2]) * 0.5f;
    const float D = pd[0];
    // Third-derivative jumps at internal knots y = 1,2,3,4.
    const float E1 = pd[1] - pd[0];
    const float E2 = pd[2] - pd[1];
    const float E3 = pd[3] - pd[2];
    const float E4 = pd[4] - pd[3];

    const float gstart = __ldg(&grid[3]);                       // left edge of valid range
    const float invh   = 1.0f / (__ldg(&grid[1]) - __ldg(&grid[0]));
    const float c0     = -gstart * invh;                        // y = x*invh + c0

    const int b0 = blockIdx.y * ROWS;
    const float* xp = x   + (size_t)b0 * S_TOTAL + s;
    float*       op = out + (size_t)b0 * S_TOTAL + s;

    #pragma unroll 1
    for (int r = 0; r < ROWS; r += UN) {
        float xv[UN];
        #pragma unroll
        for (int k = 0; k < UN; k++)
            xv[k] = xp[(size_t)k * S_TOTAL];       // MLP = UN outstanding loads

        #pragma unroll
        for (int k = 0; k < UN; k++) {
            float y = fmaf(xv[k], invh, c0);

            // Base cubic (Horner)
            float v = fmaf(fmaf(fmaf(D, y, C), y, B), y, A);

            // Truncated cubic corrections (independent, no branches)
            float r1 = fmaxf(y - 1.0f, 0.0f);
            float r2 = fmaxf(y - 2.0f, 0.0f);
            float r3 = fmaxf(y - 3.0f, 0.0f);
            float r4 = fmaxf(y - 4.0f, 0.0f);
            float t1 = r1 * r1 * r1;
            float t2 = r2 * r2 * r2;
            float t3 = r3 * r3 * r3;
            float t4 = r4 * r4 * r4;
            v = fmaf(E1, t1, v);
            v = fmaf(E2, t2, v);
            v = fmaf(E3, t3, v);
            v = fmaf(E4, t4, v);

            op[(size_t)k * S_TOTAL] = v;
        }
        xp += (size_t)UN * S_TOTAL;
        op += (size_t)UN * S_TOTAL;
    }
}

extern "C" void kernel_launch(void* const* d_in, const int* in_sizes, int n_in,
                              void* d_out, int out_size)
{
    const float* x     = (const float*)d_in[0];
    const float* coeff = (const float*)d_in[1];
    const float* grid  = (const float*)d_in[2];
    float*       out   = (float*)d_out;

    dim3 g(GRID_X, GRID_Y);   // (16, 128) = 2048 blocks
    bspline_kernel<<<g, THREADS>>>(x, coeff, grid, out);
}